// round 1
// baseline (speedup 1.0000x reference)
#include <cuda_runtime.h>
#include <math.h>

// Problem dims
#define LAYERS 6
#define DMODEL 1024
#define NHEAD  16
#define HDIM   64
#define ROTD   16
#define IFF    4096
#define VOCAB  50304
#define BATCH  2
#define SEQ    1024
#define NTOK   (BATCH*SEQ)        // 2048
#define LN_EPS 1e-5f
#define INV_SCALE 0.125f          // 1/sqrt(64)

// ---------------- scratch (static device globals; no allocation) -------------
__device__ float g_x[NTOK*DMODEL];
__device__ float g_h[NTOK*DMODEL];
__device__ float g_qkv[NTOK*3*DMODEL];
__device__ float g_q[NTOK*DMODEL];
__device__ float g_k[NTOK*DMODEL];
__device__ float g_v[NTOK*DMODEL];
__device__ float g_scores[(size_t)BATCH*NHEAD*SEQ*SEQ];   // 134 MB
__device__ float g_attO[NTOK*DMODEL];
__device__ float g_merged[NTOK*DMODEL];
__device__ float g_attd[NTOK*DMODEL];
__device__ float g_m1[NTOK*IFF];
__device__ float g_m2[NTOK*DMODEL];

// ---------------- reductions -------------------------------------------------
__device__ __forceinline__ float blockReduceSum(float v) {
    __shared__ float sh[8];
    int lane = threadIdx.x & 31, wid = threadIdx.x >> 5;
    #pragma unroll
    for (int o = 16; o; o >>= 1) v += __shfl_xor_sync(0xffffffffu, v, o);
    if (lane == 0) sh[wid] = v;
    __syncthreads();
    float r = 0.f;
    #pragma unroll
    for (int i = 0; i < 8; i++) r += sh[i];
    __syncthreads();
    return r;
}

__device__ __forceinline__ float blockReduceMax(float v) {
    __shared__ float sh[8];
    int lane = threadIdx.x & 31, wid = threadIdx.x >> 5;
    #pragma unroll
    for (int o = 16; o; o >>= 1) v = fmaxf(v, __shfl_xor_sync(0xffffffffu, v, o));
    if (lane == 0) sh[wid] = v;
    __syncthreads();
    float r = -1e30f;
    #pragma unroll
    for (int i = 0; i < 8; i++) r = fmaxf(r, sh[i]);
    __syncthreads();
    return r;
}

__device__ __forceinline__ float gelu_exact(float x) {
    return 0.5f * x * (1.f + erff(x * 0.70710678118654752f));
}

// ---------------- GEMM: C[M,N] = alpha * A[M,K] @ op(B) + bias ---------------
// TRANSB=0: B is [K,N] row-major.  TRANSB=1: B is [N,K] row-major (B^T).
// EPI=0: bias only (bias may be null). EPI=1: bias + exact GELU.
// Assumes M % 128 == 0 and K % 16 == 0 (true for every call here). N guarded.
#define BM 128
#define BN 128
#define BK 16

template<int TRANSB, int EPI>
__global__ void __launch_bounds__(256)
gemm_k(const float* __restrict__ A, const float* __restrict__ Bm,
       const float* __restrict__ bias, float* __restrict__ C,
       int M, int N, int K,
       long long sA, long long sB, long long sC, float alpha)
{
    __shared__ __align__(16) float As[BK][BM + 4];
    __shared__ __align__(16) float Bs[BK][BN + 4];

    A  += (long long)blockIdx.z * sA;
    Bm += (long long)blockIdx.z * sB;
    C  += (long long)blockIdx.z * sC;

    const int bm = blockIdx.y * BM;
    const int bn = blockIdx.x * BN;
    const int tid = threadIdx.x;
    const int tx = tid & 15;    // column group
    const int ty = tid >> 4;    // row group

    float acc[8][8];
    #pragma unroll
    for (int i = 0; i < 8; i++)
        #pragma unroll
        for (int j = 0; j < 8; j++) acc[i][j] = 0.f;

    for (int k0 = 0; k0 < K; k0 += BK) {
        // ---- load A tile (128x16) : 512 float4, 2 per thread ----
        #pragma unroll
        for (int i = 0; i < 2; i++) {
            int f = i * 256 + tid;
            int row = f >> 2, c = f & 3;
            float4 v = *(const float4*)(A + (long long)(bm + row) * K + k0 + c * 4);
            As[c*4+0][row] = v.x; As[c*4+1][row] = v.y;
            As[c*4+2][row] = v.z; As[c*4+3][row] = v.w;
        }
        // ---- load B tile (16x128) ----
        if (TRANSB == 0) {
            #pragma unroll
            for (int i = 0; i < 2; i++) {
                int f = i * 256 + tid;
                int kk = f >> 5, n4 = f & 31;
                int col = bn + n4 * 4;
                float4 v = make_float4(0.f, 0.f, 0.f, 0.f);
                if (col < N)
                    v = *(const float4*)(Bm + (long long)(k0 + kk) * N + col);
                *(float4*)&Bs[kk][n4 * 4] = v;
            }
        } else {
            #pragma unroll
            for (int i = 0; i < 2; i++) {
                int f = i * 256 + tid;
                int n = f >> 2, c = f & 3;
                float4 v = make_float4(0.f, 0.f, 0.f, 0.f);
                if (bn + n < N)
                    v = *(const float4*)(Bm + (long long)(bn + n) * K + k0 + c * 4);
                Bs[c*4+0][n] = v.x; Bs[c*4+1][n] = v.y;
                Bs[c*4+2][n] = v.z; Bs[c*4+3][n] = v.w;
            }
        }
        __syncthreads();

        // ---- compute ----
        #pragma unroll
        for (int kk = 0; kk < BK; kk++) {
            float ra[8], rb[8];
            float4 a0 = *(const float4*)&As[kk][ty * 4];
            float4 a1 = *(const float4*)&As[kk][ty * 4 + 64];
            ra[0]=a0.x; ra[1]=a0.y; ra[2]=a0.z; ra[3]=a0.w;
            ra[4]=a1.x; ra[5]=a1.y; ra[6]=a1.z; ra[7]=a1.w;
            float4 b0 = *(const float4*)&Bs[kk][tx * 4];
            float4 b1 = *(const float4*)&Bs[kk][tx * 4 + 64];
            rb[0]=b0.x; rb[1]=b0.y; rb[2]=b0.z; rb[3]=b0.w;
            rb[4]=b1.x; rb[5]=b1.y; rb[6]=b1.z; rb[7]=b1.w;
            #pragma unroll
            for (int i = 0; i < 8; i++)
                #pragma unroll
                for (int j = 0; j < 8; j++)
                    acc[i][j] = fmaf(ra[i], rb[j], acc[i][j]);
        }
        __syncthreads();
    }

    // ---- epilogue ----
    #pragma unroll
    for (int i = 0; i < 8; i++) {
        int row = bm + ty * 4 + ((i >= 4) ? 64 : 0) + (i & 3);
        #pragma unroll
        for (int jh = 0; jh < 2; jh++) {
            int col = bn + tx * 4 + jh * 64;
            if (col < N) {
                float v0 = acc[i][jh*4+0] * alpha;
                float v1 = acc[i][jh*4+1] * alpha;
                float v2 = acc[i][jh*4+2] * alpha;
                float v3 = acc[i][jh*4+3] * alpha;
                if (bias) {
                    v0 += bias[col+0]; v1 += bias[col+1];
                    v2 += bias[col+2]; v3 += bias[col+3];
                }
                if (EPI == 1) {
                    v0 = gelu_exact(v0); v1 = gelu_exact(v1);
                    v2 = gelu_exact(v2); v3 = gelu_exact(v3);
                }
                float4 out = make_float4(v0, v1, v2, v3);
                *(float4*)(C + (long long)row * N + col) = out;
            }
        }
    }
}

// ---------------- elementwise kernels ----------------------------------------
__global__ void embed_k(const int* __restrict__ ids,
                        const float* __restrict__ ew, float* __restrict__ x)
{
    int idx = blockIdx.x * blockDim.x + threadIdx.x;      // over NTOK*D
    if (idx >= NTOK * DMODEL) return;
    int row = idx / DMODEL, d = idx % DMODEL;
    x[idx] = ew[(long long)ids[row] * DMODEL + d];
}

__global__ void ln_k(const float* __restrict__ x, const float* __restrict__ s,
                     const float* __restrict__ b, float* __restrict__ out)
{
    int row = blockIdx.x;                                  // NTOK rows, 256 thr
    const float4* xr = (const float4*)(x + (long long)row * DMODEL);
    float4 v = xr[threadIdx.x];
    float sum = v.x + v.y + v.z + v.w;
    float mean = blockReduceSum(sum) * (1.f / DMODEL);
    float dx = v.x - mean, dy = v.y - mean, dz = v.z - mean, dw = v.w - mean;
    float var = blockReduceSum(dx*dx + dy*dy + dz*dz + dw*dw) * (1.f / DMODEL);
    float r = rsqrtf(var + LN_EPS);
    float4 s4 = ((const float4*)s)[threadIdx.x];
    float4 b4 = ((const float4*)b)[threadIdx.x];
    float4 o;
    o.x = dx * r * s4.x + b4.x;
    o.y = dy * r * s4.y + b4.y;
    o.z = dz * r * s4.z + b4.z;
    o.w = dw * r * s4.w + b4.w;
    ((float4*)(out + (long long)row * DMODEL))[threadIdx.x] = o;
}

// qkv [B,T,3D] -> rope applied q,k; split into Q,K,V each [B,H,T,HS]
__global__ void rope_split_k(const float* __restrict__ qkv,
                             float* __restrict__ Q, float* __restrict__ K,
                             float* __restrict__ V)
{
    int idx = blockIdx.x * blockDim.x + threadIdx.x;       // over B*H*T*HS
    if (idx >= NTOK * DMODEL) return;
    int d = idx & (HDIM - 1);
    int t = (idx >> 6) & (SEQ - 1);
    int h = (idx >> 16) & (NHEAD - 1);
    int b = idx >> 20;
    long long base = ((long long)(b * SEQ + t)) * (3 * DMODEL) + h * (3 * HDIM);
    float qv = qkv[base + d];
    float kv = qkv[base + HDIM + d];
    float vv = qkv[base + 2 * HDIM + d];
    if (d < ROTD) {
        int fi = d & 7;
        float inv = expf(-(float)(2 * fi) / ROTD * logf(10000.0f));
        float ang = (float)t * inv;
        float c = cosf(ang), s = sinf(ang);
        int partner = (d < 8) ? d + 8 : d - 8;
        float qp = qkv[base + partner];
        float kp = qkv[base + HDIM + partner];
        float rq = (d < 8) ? -qp : qp;
        float rk = (d < 8) ? -kp : kp;
        qv = qv * c + rq * s;
        kv = kv * c + rk * s;
    }
    Q[idx] = qv; K[idx] = kv; V[idx] = vv;
}

// causal softmax in place on scores [B*H*T, T]
__global__ void softmax_k(float* __restrict__ sc)
{
    long long r = blockIdx.x;                              // B*H*T rows
    int i = (int)(r & (SEQ - 1));
    float* row = sc + r * SEQ;
    int tid = threadIdx.x;                                 // 256 threads
    float mx = -1e30f;
    for (int j = tid; j <= i; j += 256) mx = fmaxf(mx, row[j]);
    mx = blockReduceMax(mx);
    float sum = 0.f;
    for (int j = tid; j <= i; j += 256) {
        float e = expf(row[j] - mx);
        row[j] = e;
        sum += e;
    }
    sum = blockReduceSum(sum);
    float inv = 1.f / sum;
    for (int j = tid; j < SEQ; j += 256)
        row[j] = (j <= i) ? row[j] * inv : 0.f;
}

// attO [B,H,T,HS] -> merged [B,T,D]
__global__ void merge_k(const float* __restrict__ o, float* __restrict__ m)
{
    int idx = blockIdx.x * blockDim.x + threadIdx.x;
    if (idx >= NTOK * DMODEL) return;
    int d = idx & (HDIM - 1);
    int t = (idx >> 6) & (SEQ - 1);
    int h = (idx >> 16) & (NHEAD - 1);
    int b = idx >> 20;
    m[(long long)(b * SEQ + t) * DMODEL + h * HDIM + d] = o[idx];
}

// x += a + c
__global__ void add3_k(float* __restrict__ x, const float* __restrict__ a,
                       const float* __restrict__ c)
{
    int idx = blockIdx.x * blockDim.x + threadIdx.x;       // over NTOK*D/4
    if (idx >= NTOK * DMODEL / 4) return;
    float4 xv = ((const float4*)x)[idx];
    float4 av = ((const float4*)a)[idx];
    float4 cv = ((const float4*)c)[idx];
    xv.x += av.x + cv.x; xv.y += av.y + cv.y;
    xv.z += av.z + cv.z; xv.w += av.w + cv.w;
    ((float4*)x)[idx] = xv;
}

// ---------------- driver ------------------------------------------------------
extern "C" void kernel_launch(void* const* d_in, const int* in_sizes, int n_in,
                              void* d_out, int out_size)
{
    const int*   ids     = (const int*)  d_in[0];
    const float* embed_w = (const float*)d_in[1];
    const float* ln1_s   = (const float*)d_in[2];
    const float* ln1_b   = (const float*)d_in[3];
    const float* ln2_s   = (const float*)d_in[4];
    const float* ln2_b   = (const float*)d_in[5];
    const float* qkv_w   = (const float*)d_in[6];
    const float* qkv_b   = (const float*)d_in[7];
    const float* dense_w = (const float*)d_in[8];
    const float* dense_b = (const float*)d_in[9];
    const float* fc1_w   = (const float*)d_in[10];
    const float* fc1_b   = (const float*)d_in[11];
    const float* fc2_w   = (const float*)d_in[12];
    const float* fc2_b   = (const float*)d_in[13];
    const float* fln_s   = (const float*)d_in[14];
    const float* fln_b   = (const float*)d_in[15];
    const float* head_w  = (const float*)d_in[16];
    float* out = (float*)d_out;

    float *x, *h, *qkv, *Q, *K, *V, *sc, *aO, *mg, *ad, *m1, *m2;
    cudaGetSymbolAddress((void**)&x,   g_x);
    cudaGetSymbolAddress((void**)&h,   g_h);
    cudaGetSymbolAddress((void**)&qkv, g_qkv);
    cudaGetSymbolAddress((void**)&Q,   g_q);
    cudaGetSymbolAddress((void**)&K,   g_k);
    cudaGetSymbolAddress((void**)&V,   g_v);
    cudaGetSymbolAddress((void**)&sc,  g_scores);
    cudaGetSymbolAddress((void**)&aO,  g_attO);
    cudaGetSymbolAddress((void**)&mg,  g_merged);
    cudaGetSymbolAddress((void**)&ad,  g_attd);
    cudaGetSymbolAddress((void**)&m1,  g_m1);
    cudaGetSymbolAddress((void**)&m2,  g_m2);

    const int ELTS = NTOK * DMODEL;                        // 2M

    embed_k<<<(ELTS + 255) / 256, 256>>>(ids, embed_w, x);

    for (int l = 0; l < LAYERS; l++) {
        // ---- attention branch ----
        ln_k<<<NTOK, 256>>>(x, ln1_s + l * DMODEL, ln1_b + l * DMODEL, h);
        gemm_k<0,0><<<dim3(3 * DMODEL / BN, NTOK / BM, 1), 256>>>(
            h, qkv_w + (size_t)l * DMODEL * 3 * DMODEL,
            qkv_b + (size_t)l * 3 * DMODEL, qkv,
            NTOK, 3 * DMODEL, DMODEL, 0, 0, 0, 1.f);
        rope_split_k<<<(ELTS + 255) / 256, 256>>>(qkv, Q, K, V);
        // scores = Q K^T / sqrt(HS), batched over B*H
        gemm_k<1,0><<<dim3(SEQ / BN, SEQ / BM, BATCH * NHEAD), 256>>>(
            Q, K, nullptr, sc,
            SEQ, SEQ, HDIM,
            (long long)SEQ * HDIM, (long long)SEQ * HDIM,
            (long long)SEQ * SEQ, INV_SCALE);
        softmax_k<<<BATCH * NHEAD * SEQ, 256>>>(sc);
        // O = P V
        gemm_k<0,0><<<dim3(1, SEQ / BM, BATCH * NHEAD), 256>>>(
            sc, V, nullptr, aO,
            SEQ, HDIM, SEQ,
            (long long)SEQ * SEQ, (long long)SEQ * HDIM,
            (long long)SEQ * HDIM, 1.f);
        merge_k<<<(ELTS + 255) / 256, 256>>>(aO, mg);
        gemm_k<0,0><<<dim3(DMODEL / BN, NTOK / BM, 1), 256>>>(
            mg, dense_w + (size_t)l * DMODEL * DMODEL,
            dense_b + (size_t)l * DMODEL, ad,
            NTOK, DMODEL, DMODEL, 0, 0, 0, 1.f);
        // ---- MLP branch (on original x) ----
        ln_k<<<NTOK, 256>>>(x, ln2_s + l * DMODEL, ln2_b + l * DMODEL, h);
        gemm_k<0,1><<<dim3(IFF / BN, NTOK / BM, 1), 256>>>(
            h, fc1_w + (size_t)l * DMODEL * IFF,
            fc1_b + (size_t)l * IFF, m1,
            NTOK, IFF, DMODEL, 0, 0, 0, 1.f);
        gemm_k<0,0><<<dim3(DMODEL / BN, NTOK / BM, 1), 256>>>(
            m1, fc2_w + (size_t)l * IFF * DMODEL,
            fc2_b + (size_t)l * DMODEL, m2,
            NTOK, DMODEL, IFF, 0, 0, 0, 1.f);
        // ---- residual: x = x + attn_out + mlp_out ----
        add3_k<<<(ELTS / 4 + 255) / 256, 256>>>(x, ad, m2);
    }

    // final LN + head
    ln_k<<<NTOK, 256>>>(x, fln_s, fln_b, h);
    gemm_k<0,0><<<dim3(VOCAB / BN, NTOK / BM, 1), 256>>>(
        h, head_w, nullptr, out,
        NTOK, VOCAB, DMODEL, 0, 0, 0, 1.f);
}

// round 2
// speedup vs baseline: 1.6553x; 1.6553x over previous
#include <cuda_runtime.h>
#include <math.h>

// Problem dims
#define LAYERS 6
#define DMODEL 1024
#define NHEAD  16
#define HDIM   64
#define ROTD   16
#define IFF    4096
#define VOCAB  50304
#define BATCH  2
#define SEQ    1024
#define NTOK   (BATCH*SEQ)        // 2048
#define LN_EPS 1e-5f
#define INV_SCALE 0.125f          // 1/sqrt(64)

// ---------------- scratch (static device globals; no allocation) -------------
__device__ float g_x[NTOK*DMODEL];
__device__ float g_h[NTOK*DMODEL];
__device__ float g_qkv[NTOK*3*DMODEL];
__device__ float g_q[NTOK*DMODEL];
__device__ float g_k[NTOK*DMODEL];
__device__ float g_v[NTOK*DMODEL];
__device__ float g_scores[(size_t)BATCH*NHEAD*SEQ*SEQ];   // 134 MB
__device__ float g_attO[NTOK*DMODEL];
__device__ float g_merged[NTOK*DMODEL];
__device__ float g_attd[NTOK*DMODEL];
__device__ float g_m1[NTOK*IFF];
__device__ float g_m2[NTOK*DMODEL];

// ---------------- reductions -------------------------------------------------
__device__ __forceinline__ float blockReduceSum(float v) {
    __shared__ float sh[8];
    int lane = threadIdx.x & 31, wid = threadIdx.x >> 5;
    #pragma unroll
    for (int o = 16; o; o >>= 1) v += __shfl_xor_sync(0xffffffffu, v, o);
    if (lane == 0) sh[wid] = v;
    __syncthreads();
    float r = 0.f;
    #pragma unroll
    for (int i = 0; i < 8; i++) r += sh[i];
    __syncthreads();
    return r;
}

__device__ __forceinline__ float blockReduceMax(float v) {
    __shared__ float sh[8];
    int lane = threadIdx.x & 31, wid = threadIdx.x >> 5;
    #pragma unroll
    for (int o = 16; o; o >>= 1) v = fmaxf(v, __shfl_xor_sync(0xffffffffu, v, o));
    if (lane == 0) sh[wid] = v;
    __syncthreads();
    float r = -1e30f;
    #pragma unroll
    for (int i = 0; i < 8; i++) r = fmaxf(r, sh[i]);
    __syncthreads();
    return r;
}

__device__ __forceinline__ float gelu_exact(float x) {
    return 0.5f * x * (1.f + erff(x * 0.70710678118654752f));
}

// ---------------- tensor-core helpers ----------------------------------------
__device__ __forceinline__ unsigned f2tf(float x) {
    unsigned u;
    asm("cvt.rna.tf32.f32 %0, %1;" : "=r"(u) : "f"(x));
    return u;
}

__device__ __forceinline__ void mma8(float* c, const unsigned* a,
                                     unsigned b0, unsigned b1) {
    asm volatile(
        "mma.sync.aligned.m16n8k8.row.col.f32.tf32.tf32.f32 "
        "{%0,%1,%2,%3},{%4,%5,%6,%7},{%8,%9},{%0,%1,%2,%3};"
        : "+f"(c[0]), "+f"(c[1]), "+f"(c[2]), "+f"(c[3])
        : "r"(a[0]), "r"(a[1]), "r"(a[2]), "r"(a[3]), "r"(b0), "r"(b1));
}

__device__ __forceinline__ void cp16(float* smem, const float* g, int sz) {
    unsigned s = (unsigned)__cvta_generic_to_shared(smem);
    asm volatile("cp.async.cg.shared.global [%0], [%1], 16, %2;\n"
                 :: "r"(s), "l"(g), "r"(sz));
}
__device__ __forceinline__ void cpcommit() {
    asm volatile("cp.async.commit_group;\n" ::);
}
__device__ __forceinline__ void cpwait0() {
    asm volatile("cp.async.wait_group 0;\n" ::: "memory");
}

// ---------------- tf32 tensor-core GEMM --------------------------------------
// C[M,N] = alpha * A[M,K] @ op(B) + bias, batched via blockIdx.z strides.
// TRANSB=0: B is [K,N].  TRANSB=1: B is [N,K] (B^T).
// EPI=1: bias + exact GELU.
// Requirements: M%128==0, K%32==0, K%4==0 16B-aligned rows (all calls satisfy).
#define BM 128
#define BN 128
#define BKT 32
#define PAD 4

template<int TRANSB, int EPI>
__global__ void __launch_bounds__(256)
gemm_tc(const float* __restrict__ A, const float* __restrict__ B,
        const float* __restrict__ bias, float* __restrict__ C,
        int M, int N, int K,
        long long sA, long long sB, long long sC, float alpha)
{
    constexpr int AP  = BKT + PAD;                 // 36
    constexpr int BPr = TRANSB ? BN : BKT;         // rows of B tile in smem
    constexpr int BPc = TRANSB ? (BKT + PAD) : (BN + PAD);

    extern __shared__ float smemf[];
    float* Asm = smemf;                            // [2][BM][AP]
    float* Bsm = smemf + 2 * BM * AP;              // [2][BPr][BPc]

    A += (long long)blockIdx.z * sA;
    B += (long long)blockIdx.z * sB;
    C += (long long)blockIdx.z * sC;

    const int bm = blockIdx.y * BM;
    const int bn = blockIdx.x * BN;
    const int tid = threadIdx.x;
    const int lane = tid & 31, w = tid >> 5;
    const int wr = w >> 1, wc = w & 1;
    const int gid = lane >> 2, tig = lane & 3;
    const int m0 = wr * 32, n0 = wc * 64;

    float acc[2][8][4];
    #pragma unroll
    for (int i = 0; i < 2; i++)
        #pragma unroll
        for (int j = 0; j < 8; j++)
            #pragma unroll
            for (int q = 0; q < 4; q++) acc[i][j][q] = 0.f;

    auto loadT = [&](int buf, int k0) {
        // A tile: 128x32 floats = 1024 float4; 4 per thread
        #pragma unroll
        for (int i = 0; i < 4; i++) {
            int idx = i * 256 + tid;
            int r = idx >> 3, c4 = (idx & 7) * 4;
            cp16(Asm + buf * BM * AP + r * AP + c4,
                 A + (long long)(bm + r) * K + k0 + c4, 16);
        }
        if (TRANSB) {
            // B^T tile: rows = n (128), cols = k (32)
            #pragma unroll
            for (int i = 0; i < 4; i++) {
                int idx = i * 256 + tid;
                int n = idx >> 3, c4 = (idx & 7) * 4;
                cp16(Bsm + buf * BPr * BPc + n * BPc + c4,
                     B + (long long)(bn + n) * K + k0 + c4, 16);
            }
        } else {
            // B tile: rows = k (32), cols = n (128)
            #pragma unroll
            for (int i = 0; i < 4; i++) {
                int idx = i * 256 + tid;
                int k = idx >> 5, n4 = (idx & 31) * 4;
                int col = bn + n4;
                const float* src = B + (long long)(k0 + k) * N + (col < N ? col : 0);
                cp16(Bsm + buf * BPr * BPc + k * BPc + n4, src, col < N ? 16 : 0);
            }
        }
        cpcommit();
    };

    loadT(0, 0);
    const int nk = K / BKT;
    for (int t = 0; t < nk; t++) {
        cpwait0();
        __syncthreads();
        if (t + 1 < nk) loadT((t + 1) & 1, (t + 1) * BKT);

        const float* Ab = Asm + (t & 1) * BM * AP;
        const float* Bb = Bsm + (t & 1) * BPr * BPc;

        #pragma unroll
        for (int ks = 0; ks < BKT / 8; ks++) {
            const int k = ks * 8;
            unsigned af[2][4];
            #pragma unroll
            for (int mt = 0; mt < 2; mt++) {
                int r = m0 + mt * 16 + gid;
                af[mt][0] = f2tf(Ab[r * AP + k + tig]);
                af[mt][1] = f2tf(Ab[(r + 8) * AP + k + tig]);
                af[mt][2] = f2tf(Ab[r * AP + k + tig + 4]);
                af[mt][3] = f2tf(Ab[(r + 8) * AP + k + tig + 4]);
            }
            #pragma unroll
            for (int nt = 0; nt < 8; nt++) {
                int c = n0 + nt * 8 + gid;
                unsigned b0, b1;
                if (TRANSB) {
                    b0 = f2tf(Bb[c * BPc + k + tig]);
                    b1 = f2tf(Bb[c * BPc + k + tig + 4]);
                } else {
                    b0 = f2tf(Bb[(k + tig) * BPc + c]);
                    b1 = f2tf(Bb[(k + tig + 4) * BPc + c]);
                }
                mma8(acc[0][nt], af[0], b0, b1);
                mma8(acc[1][nt], af[1], b0, b1);
            }
        }
        __syncthreads();
    }

    // ---- epilogue ----
    #pragma unroll
    for (int mt = 0; mt < 2; mt++) {
        const int r0 = bm + m0 + mt * 16 + gid;
        #pragma unroll
        for (int nt = 0; nt < 8; nt++) {
            int c = bn + n0 + nt * 8 + 2 * tig;
            if (c < N) {
                float* a4 = acc[mt][nt];
                float v0 = a4[0] * alpha, v1 = a4[1] * alpha;
                float v2 = a4[2] * alpha, v3 = a4[3] * alpha;
                if (bias) {
                    float bv0 = bias[c], bv1 = bias[c + 1];
                    v0 += bv0; v1 += bv1; v2 += bv0; v3 += bv1;
                }
                if (EPI == 1) {
                    v0 = gelu_exact(v0); v1 = gelu_exact(v1);
                    v2 = gelu_exact(v2); v3 = gelu_exact(v3);
                }
                *(float2*)(C + (long long)r0 * N + c) = make_float2(v0, v1);
                *(float2*)(C + (long long)(r0 + 8) * N + c) = make_float2(v2, v3);
            }
        }
    }
}

// ---------------- elementwise kernels ----------------------------------------
__global__ void embed_k(const int* __restrict__ ids,
                        const float* __restrict__ ew, float* __restrict__ x)
{
    int idx = blockIdx.x * blockDim.x + threadIdx.x;      // over NTOK*D
    if (idx >= NTOK * DMODEL) return;
    int row = idx / DMODEL, d = idx % DMODEL;
    x[idx] = ew[(long long)ids[row] * DMODEL + d];
}

__global__ void ln_k(const float* __restrict__ x, const float* __restrict__ s,
                     const float* __restrict__ b, float* __restrict__ out)
{
    int row = blockIdx.x;                                  // NTOK rows, 256 thr
    const float4* xr = (const float4*)(x + (long long)row * DMODEL);
    float4 v = xr[threadIdx.x];
    float sum = v.x + v.y + v.z + v.w;
    float mean = blockReduceSum(sum) * (1.f / DMODEL);
    float dx = v.x - mean, dy = v.y - mean, dz = v.z - mean, dw = v.w - mean;
    float var = blockReduceSum(dx*dx + dy*dy + dz*dz + dw*dw) * (1.f / DMODEL);
    float r = rsqrtf(var + LN_EPS);
    float4 s4 = ((const float4*)s)[threadIdx.x];
    float4 b4 = ((const float4*)b)[threadIdx.x];
    float4 o;
    o.x = dx * r * s4.x + b4.x;
    o.y = dy * r * s4.y + b4.y;
    o.z = dz * r * s4.z + b4.z;
    o.w = dw * r * s4.w + b4.w;
    ((float4*)(out + (long long)row * DMODEL))[threadIdx.x] = o;
}

// qkv [B,T,3D] -> rope applied q,k; split into Q,K,V each [B,H,T,HS]
__global__ void rope_split_k(const float* __restrict__ qkv,
                             float* __restrict__ Q, float* __restrict__ K,
                             float* __restrict__ V)
{
    int idx = blockIdx.x * blockDim.x + threadIdx.x;       // over B*H*T*HS
    if (idx >= NTOK * DMODEL) return;
    int d = idx & (HDIM - 1);
    int t = (idx >> 6) & (SEQ - 1);
    int h = (idx >> 16) & (NHEAD - 1);
    int b = idx >> 20;
    long long base = ((long long)(b * SEQ + t)) * (3 * DMODEL) + h * (3 * HDIM);
    float qv = qkv[base + d];
    float kv = qkv[base + HDIM + d];
    float vv = qkv[base + 2 * HDIM + d];
    if (d < ROTD) {
        int fi = d & 7;
        float inv = expf(-(float)(2 * fi) / ROTD * logf(10000.0f));
        float ang = (float)t * inv;
        float c = cosf(ang), s = sinf(ang);
        int partner = (d < 8) ? d + 8 : d - 8;
        float qp = qkv[base + partner];
        float kp = qkv[base + HDIM + partner];
        float rq = (d < 8) ? -qp : qp;
        float rk = (d < 8) ? -kp : kp;
        qv = qv * c + rq * s;
        kv = kv * c + rk * s;
    }
    Q[idx] = qv; K[idx] = kv; V[idx] = vv;
}

// causal softmax in place on scores [B*H*T, T]
__global__ void softmax_k(float* __restrict__ sc)
{
    long long r = blockIdx.x;                              // B*H*T rows
    int i = (int)(r & (SEQ - 1));
    float* row = sc + r * SEQ;
    int tid = threadIdx.x;                                 // 256 threads
    float mx = -1e30f;
    for (int j = tid; j <= i; j += 256) mx = fmaxf(mx, row[j]);
    mx = blockReduceMax(mx);
    float sum = 0.f;
    for (int j = tid; j <= i; j += 256) {
        float e = expf(row[j] - mx);
        row[j] = e;
        sum += e;
    }
    sum = blockReduceSum(sum);
    float inv = 1.f / sum;
    for (int j = tid; j < SEQ; j += 256)
        row[j] = (j <= i) ? row[j] * inv : 0.f;
}

// attO [B,H,T,HS] -> merged [B,T,D]
__global__ void merge_k(const float* __restrict__ o, float* __restrict__ m)
{
    int idx = blockIdx.x * blockDim.x + threadIdx.x;
    if (idx >= NTOK * DMODEL) return;
    int d = idx & (HDIM - 1);
    int t = (idx >> 6) & (SEQ - 1);
    int h = (idx >> 16) & (NHEAD - 1);
    int b = idx >> 20;
    m[(long long)(b * SEQ + t) * DMODEL + h * HDIM + d] = o[idx];
}

// x += a + c
__global__ void add3_k(float* __restrict__ x, const float* __restrict__ a,
                       const float* __restrict__ c)
{
    int idx = blockIdx.x * blockDim.x + threadIdx.x;       // over NTOK*D/4
    if (idx >= NTOK * DMODEL / 4) return;
    float4 xv = ((const float4*)x)[idx];
    float4 av = ((const float4*)a)[idx];
    float4 cv = ((const float4*)c)[idx];
    xv.x += av.x + cv.x; xv.y += av.y + cv.y;
    xv.z += av.z + cv.z; xv.w += av.w + cv.w;
    ((float4*)x)[idx] = xv;
}

// smem sizes for the two B-layout variants
#define SMEM_T0 ((2*BM*(BKT+PAD) + 2*BKT*(BN+PAD)) * 4)    // 70656
#define SMEM_T1 ((2*BM*(BKT+PAD) + 2*BN*(BKT+PAD)) * 4)    // 73728

// ---------------- driver ------------------------------------------------------
extern "C" void kernel_launch(void* const* d_in, const int* in_sizes, int n_in,
                              void* d_out, int out_size)
{
    const int*   ids     = (const int*)  d_in[0];
    const float* embed_w = (const float*)d_in[1];
    const float* ln1_s   = (const float*)d_in[2];
    const float* ln1_b   = (const float*)d_in[3];
    const float* ln2_s   = (const float*)d_in[4];
    const float* ln2_b   = (const float*)d_in[5];
    const float* qkv_w   = (const float*)d_in[6];
    const float* qkv_b   = (const float*)d_in[7];
    const float* dense_w = (const float*)d_in[8];
    const float* dense_b = (const float*)d_in[9];
    const float* fc1_w   = (const float*)d_in[10];
    const float* fc1_b   = (const float*)d_in[11];
    const float* fc2_w   = (const float*)d_in[12];
    const float* fc2_b   = (const float*)d_in[13];
    const float* fln_s   = (const float*)d_in[14];
    const float* fln_b   = (const float*)d_in[15];
    const float* head_w  = (const float*)d_in[16];
    float* out = (float*)d_out;

    static int attr_done = 0;
    if (!attr_done) {
        cudaFuncSetAttribute(gemm_tc<0,0>, cudaFuncAttributeMaxDynamicSharedMemorySize, SMEM_T0);
        cudaFuncSetAttribute(gemm_tc<0,1>, cudaFuncAttributeMaxDynamicSharedMemorySize, SMEM_T0);
        cudaFuncSetAttribute(gemm_tc<1,0>, cudaFuncAttributeMaxDynamicSharedMemorySize, SMEM_T1);
        attr_done = 1;
    }

    float *x, *h, *qkv, *Q, *K, *V, *sc, *aO, *mg, *ad, *m1, *m2;
    cudaGetSymbolAddress((void**)&x,   g_x);
    cudaGetSymbolAddress((void**)&h,   g_h);
    cudaGetSymbolAddress((void**)&qkv, g_qkv);
    cudaGetSymbolAddress((void**)&Q,   g_q);
    cudaGetSymbolAddress((void**)&K,   g_k);
    cudaGetSymbolAddress((void**)&V,   g_v);
    cudaGetSymbolAddress((void**)&sc,  g_scores);
    cudaGetSymbolAddress((void**)&aO,  g_attO);
    cudaGetSymbolAddress((void**)&mg,  g_merged);
    cudaGetSymbolAddress((void**)&ad,  g_attd);
    cudaGetSymbolAddress((void**)&m1,  g_m1);
    cudaGetSymbolAddress((void**)&m2,  g_m2);

    const int ELTS = NTOK * DMODEL;                        // 2M

    embed_k<<<(ELTS + 255) / 256, 256>>>(ids, embed_w, x);

    for (int l = 0; l < LAYERS; l++) {
        // ---- attention branch ----
        ln_k<<<NTOK, 256>>>(x, ln1_s + l * DMODEL, ln1_b + l * DMODEL, h);
        gemm_tc<0,0><<<dim3(3 * DMODEL / BN, NTOK / BM, 1), 256, SMEM_T0>>>(
            h, qkv_w + (size_t)l * DMODEL * 3 * DMODEL,
            qkv_b + (size_t)l * 3 * DMODEL, qkv,
            NTOK, 3 * DMODEL, DMODEL, 0, 0, 0, 1.f);
        rope_split_k<<<(ELTS + 255) / 256, 256>>>(qkv, Q, K, V);
        // scores = Q K^T / sqrt(HS), batched over B*H
        gemm_tc<1,0><<<dim3(SEQ / BN, SEQ / BM, BATCH * NHEAD), 256, SMEM_T1>>>(
            Q, K, nullptr, sc,
            SEQ, SEQ, HDIM,
            (long long)SEQ * HDIM, (long long)SEQ * HDIM,
            (long long)SEQ * SEQ, INV_SCALE);
        softmax_k<<<BATCH * NHEAD * SEQ, 256>>>(sc);
        // O = P V
        gemm_tc<0,0><<<dim3(1, SEQ / BM, BATCH * NHEAD), 256, SMEM_T0>>>(
            sc, V, nullptr, aO,
            SEQ, HDIM, SEQ,
            (long long)SEQ * SEQ, (long long)SEQ * HDIM,
            (long long)SEQ * HDIM, 1.f);
        merge_k<<<(ELTS + 255) / 256, 256>>>(aO, mg);
        gemm_tc<0,0><<<dim3(DMODEL / BN, NTOK / BM, 1), 256, SMEM_T0>>>(
            mg, dense_w + (size_t)l * DMODEL * DMODEL,
            dense_b + (size_t)l * DMODEL, ad,
            NTOK, DMODEL, DMODEL, 0, 0, 0, 1.f);
        // ---- MLP branch (on original x) ----
        ln_k<<<NTOK, 256>>>(x, ln2_s + l * DMODEL, ln2_b + l * DMODEL, h);
        gemm_tc<0,1><<<dim3(IFF / BN, NTOK / BM, 1), 256, SMEM_T0>>>(
            h, fc1_w + (size_t)l * DMODEL * IFF,
            fc1_b + (size_t)l * IFF, m1,
            NTOK, IFF, DMODEL, 0, 0, 0, 1.f);
        gemm_tc<0,0><<<dim3(DMODEL / BN, NTOK / BM, 1), 256, SMEM_T0>>>(
            m1, fc2_w + (size_t)l * IFF * DMODEL,
            fc2_b + (size_t)l * DMODEL, m2,
            NTOK, DMODEL, IFF, 0, 0, 0, 1.f);
        // ---- residual: x = x + attn_out + mlp_out ----
        add3_k<<<(ELTS / 4 + 255) / 256, 256>>>(x, ad, m2);
    }

    // final LN + head
    ln_k<<<NTOK, 256>>>(x, fln_s, fln_b, h);
    gemm_tc<0,0><<<dim3(VOCAB / BN, NTOK / BM, 1), 256, SMEM_T0>>>(
        h, head_w, nullptr, out,
        NTOK, VOCAB, DMODEL, 0, 0, 0, 1.f);
}

// round 3
// speedup vs baseline: 3.3069x; 1.9978x over previous
#include <cuda_runtime.h>
#include <math.h>

// Problem dims
#define LAYERS 6
#define DMODEL 1024
#define NHEAD  16
#define HDIM   64
#define ROTD   16
#define IFF    4096
#define VOCAB  50304
#define BATCH  2
#define SEQ    1024
#define NTOK   (BATCH*SEQ)        // 2048
#define LN_EPS 1e-5f
#define INV_SCALE 0.125f          // 1/sqrt(64)

// ---------------- scratch (static device globals; no allocation) -------------
__device__ float g_x[NTOK*DMODEL];
__device__ float g_h[NTOK*DMODEL];
__device__ float g_qkv[NTOK*3*DMODEL];
__device__ float g_q[NTOK*DMODEL];
__device__ float g_k[NTOK*DMODEL];
__device__ float g_v[NTOK*DMODEL];
__device__ float g_scores[(size_t)BATCH*NHEAD*SEQ*SEQ];   // 134 MB
__device__ float g_merged[NTOK*DMODEL];
__device__ float g_attd[NTOK*DMODEL];
__device__ float g_m1[NTOK*IFF];
__device__ float g_m2[NTOK*DMODEL];

// tf32-rounded weight copies (converted once per launch)
__device__ float g_wq[(size_t)LAYERS*DMODEL*3*DMODEL];
__device__ float g_wd[(size_t)LAYERS*DMODEL*DMODEL];
__device__ float g_w1[(size_t)LAYERS*DMODEL*IFF];
__device__ float g_w2[(size_t)LAYERS*IFF*DMODEL];
__device__ float g_wh[(size_t)DMODEL*VOCAB];

// ---------------- helpers -----------------------------------------------------
__device__ __forceinline__ unsigned f2tf(float x) {
    unsigned u;
    asm("cvt.rna.tf32.f32 %0, %1;" : "=r"(u) : "f"(x));
    return u;
}
__device__ __forceinline__ float tf32r(float x) {
    return __uint_as_float(f2tf(x));
}

__device__ __forceinline__ float blockReduceSum(float v) {
    __shared__ float sh[8];
    int lane = threadIdx.x & 31, wid = threadIdx.x >> 5;
    #pragma unroll
    for (int o = 16; o; o >>= 1) v += __shfl_xor_sync(0xffffffffu, v, o);
    if (lane == 0) sh[wid] = v;
    __syncthreads();
    float r = 0.f;
    #pragma unroll
    for (int i = 0; i < 8; i++) r += sh[i];
    __syncthreads();
    return r;
}

__device__ __forceinline__ float blockReduceMax(float v) {
    __shared__ float sh[8];
    int lane = threadIdx.x & 31, wid = threadIdx.x >> 5;
    #pragma unroll
    for (int o = 16; o; o >>= 1) v = fmaxf(v, __shfl_xor_sync(0xffffffffu, v, o));
    if (lane == 0) sh[wid] = v;
    __syncthreads();
    float r = -1e30f;
    #pragma unroll
    for (int i = 0; i < 8; i++) r = fmaxf(r, sh[i]);
    __syncthreads();
    return r;
}

__device__ __forceinline__ float gelu_exact(float x) {
    return 0.5f * x * (1.f + erff(x * 0.70710678118654752f));
}

__device__ __forceinline__ void mma8(float* c, const unsigned* a,
                                     unsigned b0, unsigned b1) {
    asm volatile(
        "mma.sync.aligned.m16n8k8.row.col.f32.tf32.tf32.f32 "
        "{%0,%1,%2,%3},{%4,%5,%6,%7},{%8,%9},{%0,%1,%2,%3};"
        : "+f"(c[0]), "+f"(c[1]), "+f"(c[2]), "+f"(c[3])
        : "r"(a[0]), "r"(a[1]), "r"(a[2]), "r"(a[3]), "r"(b0), "r"(b1));
}

__device__ __forceinline__ void cp16(float* smem, const float* g, int sz) {
    unsigned s = (unsigned)__cvta_generic_to_shared(smem);
    asm volatile("cp.async.cg.shared.global [%0], [%1], 16, %2;\n"
                 :: "r"(s), "l"(g), "r"(sz));
}
__device__ __forceinline__ void cpcommit() {
    asm volatile("cp.async.commit_group;\n" ::);
}
__device__ __forceinline__ void cpwait0() {
    asm volatile("cp.async.wait_group 0;\n" ::: "memory");
}

// ---------------- tf32 tensor-core GEMM --------------------------------------
// C[M,N] = alpha * A[M,K] @ op(B) + bias.  Operands must be pre-rounded tf32.
// TRANSB=0: B is [K,N].  TRANSB=1: B is [N,K] (B^T).
// EPI bit0: exact GELU.  EPI bit1: round output to tf32.
// PVOUT=1: C base = (z>>4)*SEQ*D + (z&15)*HDIM, ldC = DMODEL (attention merge).
#define BM 128
#define BN 128
#define BKT 32
#define APAD 36      // A tile row stride (==4 mod 32 -> conflict-free frags)
#define BPAD0 136    // B tile row stride TRANSB=0 (==8 mod 32 -> conflict-free)

template<int TRANSB, int EPI, int PVOUT>
__global__ void __launch_bounds__(256, 2)
gemm_tc(const float* __restrict__ A, const float* __restrict__ B,
        const float* __restrict__ bias, float* __restrict__ C,
        int M, int N, int K,
        long long sA, long long sB, long long sC, float alpha)
{
    constexpr int AP  = APAD;
    constexpr int BPr = TRANSB ? BN : BKT;
    constexpr int BPc = TRANSB ? APAD : BPAD0;

    extern __shared__ float smemf[];
    float* Asm = smemf;                            // [2][BM][AP]
    float* Bsm = smemf + 2 * BM * AP;              // [2][BPr][BPc]

    const int bz = blockIdx.z;
    A += (long long)bz * sA;
    B += (long long)bz * sB;
    long long ldC;
    if (PVOUT) {
        C += (long long)(bz >> 4) * SEQ * DMODEL + (bz & 15) * HDIM;
        ldC = DMODEL;
    } else {
        C += (long long)bz * sC;
        ldC = N;
    }

    const int bm = blockIdx.y * BM;
    const int bn = blockIdx.x * BN;
    const int tid = threadIdx.x;
    const int lane = tid & 31, w = tid >> 5;
    const int wr = w >> 1, wc = w & 1;
    const int gid = lane >> 2, tig = lane & 3;
    const int m0 = wr * 32, n0 = wc * 64;

    float acc[2][8][4];
    #pragma unroll
    for (int i = 0; i < 2; i++)
        #pragma unroll
        for (int j = 0; j < 8; j++)
            #pragma unroll
            for (int q = 0; q < 4; q++) acc[i][j][q] = 0.f;

    auto loadT = [&](int buf, int k0) {
        #pragma unroll
        for (int i = 0; i < 4; i++) {
            int idx = i * 256 + tid;
            int r = idx >> 3, c4 = (idx & 7) * 4;
            cp16(Asm + buf * BM * AP + r * AP + c4,
                 A + (long long)(bm + r) * K + k0 + c4, 16);
        }
        if (TRANSB) {
            #pragma unroll
            for (int i = 0; i < 4; i++) {
                int idx = i * 256 + tid;
                int n = idx >> 3, c4 = (idx & 7) * 4;
                cp16(Bsm + buf * BPr * BPc + n * BPc + c4,
                     B + (long long)(bn + n) * K + k0 + c4, 16);
            }
        } else {
            #pragma unroll
            for (int i = 0; i < 4; i++) {
                int idx = i * 256 + tid;
                int k = idx >> 5, n4 = (idx & 31) * 4;
                int col = bn + n4;
                const float* src = B + (long long)(k0 + k) * N + (col < N ? col : 0);
                cp16(Bsm + buf * BPr * BPc + k * BPc + n4, src, col < N ? 16 : 0);
            }
        }
        cpcommit();
    };

    loadT(0, 0);
    const int nk = K / BKT;
    for (int t = 0; t < nk; t++) {
        cpwait0();
        __syncthreads();
        if (t + 1 < nk) loadT((t + 1) & 1, (t + 1) * BKT);

        const float* Ab = Asm + (t & 1) * BM * AP;
        const float* Bb = Bsm + (t & 1) * BPr * BPc;

        #pragma unroll
        for (int ks = 0; ks < BKT / 8; ks++) {
            const int k = ks * 8;
            unsigned af[2][4];
            #pragma unroll
            for (int mt = 0; mt < 2; mt++) {
                int r = m0 + mt * 16 + gid;
                af[mt][0] = __float_as_uint(Ab[r * AP + k + tig]);
                af[mt][1] = __float_as_uint(Ab[(r + 8) * AP + k + tig]);
                af[mt][2] = __float_as_uint(Ab[r * AP + k + tig + 4]);
                af[mt][3] = __float_as_uint(Ab[(r + 8) * AP + k + tig + 4]);
            }
            #pragma unroll
            for (int nt = 0; nt < 8; nt++) {
                int c = n0 + nt * 8 + gid;
                unsigned b0, b1;
                if (TRANSB) {
                    b0 = __float_as_uint(Bb[c * BPc + k + tig]);
                    b1 = __float_as_uint(Bb[c * BPc + k + tig + 4]);
                } else {
                    b0 = __float_as_uint(Bb[(k + tig) * BPc + c]);
                    b1 = __float_as_uint(Bb[(k + tig + 4) * BPc + c]);
                }
                mma8(acc[0][nt], af[0], b0, b1);
                mma8(acc[1][nt], af[1], b0, b1);
            }
        }
        __syncthreads();
    }

    // ---- epilogue ----
    #pragma unroll
    for (int mt = 0; mt < 2; mt++) {
        const int r0 = bm + m0 + mt * 16 + gid;
        #pragma unroll
        for (int nt = 0; nt < 8; nt++) {
            int c = bn + n0 + nt * 8 + 2 * tig;
            if (c < N) {
                float* a4 = acc[mt][nt];
                float v0 = a4[0] * alpha, v1 = a4[1] * alpha;
                float v2 = a4[2] * alpha, v3 = a4[3] * alpha;
                if (bias) {
                    float bv0 = bias[c], bv1 = bias[c + 1];
                    v0 += bv0; v1 += bv1; v2 += bv0; v3 += bv1;
                }
                if (EPI & 1) {
                    v0 = gelu_exact(v0); v1 = gelu_exact(v1);
                    v2 = gelu_exact(v2); v3 = gelu_exact(v3);
                }
                if (EPI & 2) {
                    v0 = tf32r(v0); v1 = tf32r(v1);
                    v2 = tf32r(v2); v3 = tf32r(v3);
                }
                *(float2*)(C + (long long)r0 * ldC + c) = make_float2(v0, v1);
                *(float2*)(C + (long long)(r0 + 8) * ldC + c) = make_float2(v2, v3);
            }
        }
    }
}

// ---------------- elementwise kernels ----------------------------------------
__global__ void cvtw_k(const float* __restrict__ in, float* __restrict__ out,
                       long long n4)
{
    long long i = (long long)blockIdx.x * blockDim.x + threadIdx.x;
    if (i >= n4) return;
    float4 v = ((const float4*)in)[i];
    v.x = tf32r(v.x); v.y = tf32r(v.y); v.z = tf32r(v.z); v.w = tf32r(v.w);
    ((float4*)out)[i] = v;
}

__global__ void embed_k(const int* __restrict__ ids,
                        const float* __restrict__ ew, float* __restrict__ x)
{
    int idx = blockIdx.x * blockDim.x + threadIdx.x;
    if (idx >= NTOK * DMODEL) return;
    int row = idx / DMODEL, d = idx % DMODEL;
    x[idx] = ew[(long long)ids[row] * DMODEL + d];
}

// LayerNorm; output rounded to tf32 (feeds GEMM A operand)
__global__ void ln_k(const float* __restrict__ x, const float* __restrict__ s,
                     const float* __restrict__ b, float* __restrict__ out)
{
    int row = blockIdx.x;
    const float4* xr = (const float4*)(x + (long long)row * DMODEL);
    float4 v = xr[threadIdx.x];
    float sum = v.x + v.y + v.z + v.w;
    float mean = blockReduceSum(sum) * (1.f / DMODEL);
    float dx = v.x - mean, dy = v.y - mean, dz = v.z - mean, dw = v.w - mean;
    float var = blockReduceSum(dx*dx + dy*dy + dz*dz + dw*dw) * (1.f / DMODEL);
    float r = rsqrtf(var + LN_EPS);
    float4 s4 = ((const float4*)s)[threadIdx.x];
    float4 b4 = ((const float4*)b)[threadIdx.x];
    float4 o;
    o.x = tf32r(dx * r * s4.x + b4.x);
    o.y = tf32r(dy * r * s4.y + b4.y);
    o.z = tf32r(dz * r * s4.z + b4.z);
    o.w = tf32r(dw * r * s4.w + b4.w);
    ((float4*)(out + (long long)row * DMODEL))[threadIdx.x] = o;
}

// qkv [B,T,3D] -> rope applied q,k; split into Q,K,V each [B,H,T,HS]; tf32-rounded
__global__ void rope_split_k(const float* __restrict__ qkv,
                             float* __restrict__ Q, float* __restrict__ K,
                             float* __restrict__ V)
{
    int idx = blockIdx.x * blockDim.x + threadIdx.x;
    if (idx >= NTOK * DMODEL) return;
    int d = idx & (HDIM - 1);
    int t = (idx >> 6) & (SEQ - 1);
    int h = (idx >> 16) & (NHEAD - 1);
    int b = idx >> 20;
    long long base = ((long long)(b * SEQ + t)) * (3 * DMODEL) + h * (3 * HDIM);
    float qv = qkv[base + d];
    float kv = qkv[base + HDIM + d];
    float vv = qkv[base + 2 * HDIM + d];
    if (d < ROTD) {
        int fi = d & 7;
        float inv = expf(-(float)(2 * fi) / ROTD * logf(10000.0f));
        float ang = (float)t * inv;
        float c = cosf(ang), s = sinf(ang);
        int partner = (d < 8) ? d + 8 : d - 8;
        float qp = qkv[base + partner];
        float kp = qkv[base + HDIM + partner];
        float rq = (d < 8) ? -qp : qp;
        float rk = (d < 8) ? -kp : kp;
        qv = qv * c + rq * s;
        kv = kv * c + rk * s;
    }
    Q[idx] = tf32r(qv); K[idx] = tf32r(kv); V[idx] = tf32r(vv);
}

// causal softmax in place; probabilities rounded to tf32 (feed PV GEMM)
__global__ void softmax_k(float* __restrict__ sc)
{
    long long r = blockIdx.x;
    int i = (int)(r & (SEQ - 1));
    float* row = sc + r * SEQ;
    int tid = threadIdx.x;
    float mx = -1e30f;
    for (int j = tid; j <= i; j += 256) mx = fmaxf(mx, row[j]);
    mx = blockReduceMax(mx);
    float sum = 0.f;
    for (int j = tid; j <= i; j += 256) {
        float e = expf(row[j] - mx);
        row[j] = e;
        sum += e;
    }
    sum = blockReduceSum(sum);
    float inv = 1.f / sum;
    for (int j = tid; j < SEQ; j += 256)
        row[j] = (j <= i) ? tf32r(row[j] * inv) : 0.f;
}

// x += a + c
__global__ void add3_k(float* __restrict__ x, const float* __restrict__ a,
                       const float* __restrict__ c)
{
    int idx = blockIdx.x * blockDim.x + threadIdx.x;
    if (idx >= NTOK * DMODEL / 4) return;
    float4 xv = ((const float4*)x)[idx];
    float4 av = ((const float4*)a)[idx];
    float4 cv = ((const float4*)c)[idx];
    xv.x += av.x + cv.x; xv.y += av.y + cv.y;
    xv.z += av.z + cv.z; xv.w += av.w + cv.w;
    ((float4*)x)[idx] = xv;
}

// smem sizes
#define SMEM_T0 ((2*BM*APAD + 2*BKT*BPAD0) * 4)    // 71680
#define SMEM_T1 ((2*BM*APAD + 2*BN*APAD) * 4)      // 73728

// ---------------- driver ------------------------------------------------------
extern "C" void kernel_launch(void* const* d_in, const int* in_sizes, int n_in,
                              void* d_out, int out_size)
{
    const int*   ids     = (const int*)  d_in[0];
    const float* embed_w = (const float*)d_in[1];
    const float* ln1_s   = (const float*)d_in[2];
    const float* ln1_b   = (const float*)d_in[3];
    const float* ln2_s   = (const float*)d_in[4];
    const float* ln2_b   = (const float*)d_in[5];
    const float* qkv_w   = (const float*)d_in[6];
    const float* qkv_b   = (const float*)d_in[7];
    const float* dense_w = (const float*)d_in[8];
    const float* dense_b = (const float*)d_in[9];
    const float* fc1_w   = (const float*)d_in[10];
    const float* fc1_b   = (const float*)d_in[11];
    const float* fc2_w   = (const float*)d_in[12];
    const float* fc2_b   = (const float*)d_in[13];
    const float* fln_s   = (const float*)d_in[14];
    const float* fln_b   = (const float*)d_in[15];
    const float* head_w  = (const float*)d_in[16];
    float* out = (float*)d_out;

    static int attr_done = 0;
    if (!attr_done) {
        cudaFuncSetAttribute(gemm_tc<0,0,0>, cudaFuncAttributeMaxDynamicSharedMemorySize, SMEM_T0);
        cudaFuncSetAttribute(gemm_tc<0,3,0>, cudaFuncAttributeMaxDynamicSharedMemorySize, SMEM_T0);
        cudaFuncSetAttribute(gemm_tc<0,2,1>, cudaFuncAttributeMaxDynamicSharedMemorySize, SMEM_T0);
        cudaFuncSetAttribute(gemm_tc<1,0,0>, cudaFuncAttributeMaxDynamicSharedMemorySize, SMEM_T1);
        attr_done = 1;
    }

    float *x, *h, *qkv, *Q, *K, *V, *sc, *mg, *ad, *m1, *m2;
    float *wq, *wd, *w1, *w2, *wh;
    cudaGetSymbolAddress((void**)&x,   g_x);
    cudaGetSymbolAddress((void**)&h,   g_h);
    cudaGetSymbolAddress((void**)&qkv, g_qkv);
    cudaGetSymbolAddress((void**)&Q,   g_q);
    cudaGetSymbolAddress((void**)&K,   g_k);
    cudaGetSymbolAddress((void**)&V,   g_v);
    cudaGetSymbolAddress((void**)&sc,  g_scores);
    cudaGetSymbolAddress((void**)&mg,  g_merged);
    cudaGetSymbolAddress((void**)&ad,  g_attd);
    cudaGetSymbolAddress((void**)&m1,  g_m1);
    cudaGetSymbolAddress((void**)&m2,  g_m2);
    cudaGetSymbolAddress((void**)&wq,  g_wq);
    cudaGetSymbolAddress((void**)&wd,  g_wd);
    cudaGetSymbolAddress((void**)&w1,  g_w1);
    cudaGetSymbolAddress((void**)&w2,  g_w2);
    cudaGetSymbolAddress((void**)&wh,  g_wh);

    const int ELTS = NTOK * DMODEL;

    // ---- one-shot weight rounding to tf32 ----
    {
        long long n;
        n = (long long)LAYERS*DMODEL*3*DMODEL/4;
        cvtw_k<<<(unsigned)((n+255)/256), 256>>>(qkv_w, wq, n);
        n = (long long)LAYERS*DMODEL*DMODEL/4;
        cvtw_k<<<(unsigned)((n+255)/256), 256>>>(dense_w, wd, n);
        n = (long long)LAYERS*DMODEL*IFF/4;
        cvtw_k<<<(unsigned)((n+255)/256), 256>>>(fc1_w, w1, n);
        n = (long long)LAYERS*IFF*DMODEL/4;
        cvtw_k<<<(unsigned)((n+255)/256), 256>>>(fc2_w, w2, n);
        n = (long long)DMODEL*VOCAB/4;
        cvtw_k<<<(unsigned)((n+255)/256), 256>>>(head_w, wh, n);
    }

    embed_k<<<(ELTS + 255) / 256, 256>>>(ids, embed_w, x);

    for (int l = 0; l < LAYERS; l++) {
        // ---- attention branch ----
        ln_k<<<NTOK, 256>>>(x, ln1_s + l * DMODEL, ln1_b + l * DMODEL, h);
        gemm_tc<0,0,0><<<dim3(3 * DMODEL / BN, NTOK / BM, 1), 256, SMEM_T0>>>(
            h, wq + (size_t)l * DMODEL * 3 * DMODEL,
            qkv_b + (size_t)l * 3 * DMODEL, qkv,
            NTOK, 3 * DMODEL, DMODEL, 0, 0, 0, 1.f);
        rope_split_k<<<(ELTS + 255) / 256, 256>>>(qkv, Q, K, V);
        // scores = Q K^T / sqrt(HS), batched over B*H
        gemm_tc<1,0,0><<<dim3(SEQ / BN, SEQ / BM, BATCH * NHEAD), 256, SMEM_T1>>>(
            Q, K, nullptr, sc,
            SEQ, SEQ, HDIM,
            (long long)SEQ * HDIM, (long long)SEQ * HDIM,
            (long long)SEQ * SEQ, INV_SCALE);
        softmax_k<<<BATCH * NHEAD * SEQ, 256>>>(sc);
        // O = P V, written directly in merged [B,T,D] layout (rounded)
        gemm_tc<0,2,1><<<dim3(1, SEQ / BM, BATCH * NHEAD), 256, SMEM_T0>>>(
            sc, V, nullptr, mg,
            SEQ, HDIM, SEQ,
            (long long)SEQ * SEQ, (long long)SEQ * HDIM, 0, 1.f);
        gemm_tc<0,0,0><<<dim3(DMODEL / BN, NTOK / BM, 1), 256, SMEM_T0>>>(
            mg, wd + (size_t)l * DMODEL * DMODEL,
            dense_b + (size_t)l * DMODEL, ad,
            NTOK, DMODEL, DMODEL, 0, 0, 0, 1.f);
        // ---- MLP branch (on original x) ----
        ln_k<<<NTOK, 256>>>(x, ln2_s + l * DMODEL, ln2_b + l * DMODEL, h);
        gemm_tc<0,3,0><<<dim3(IFF / BN, NTOK / BM, 1), 256, SMEM_T0>>>(
            h, w1 + (size_t)l * DMODEL * IFF,
            fc1_b + (size_t)l * IFF, m1,
            NTOK, IFF, DMODEL, 0, 0, 0, 1.f);
        gemm_tc<0,0,0><<<dim3(DMODEL / BN, NTOK / BM, 1), 256, SMEM_T0>>>(
            m1, w2 + (size_t)l * IFF * DMODEL,
            fc2_b + (size_t)l * DMODEL, m2,
            NTOK, DMODEL, IFF, 0, 0, 0, 1.f);
        // ---- residual: x = x + attn_out + mlp_out ----
        add3_k<<<(ELTS / 4 + 255) / 256, 256>>>(x, ad, m2);
    }

    // final LN + head
    ln_k<<<NTOK, 256>>>(x, fln_s, fln_b, h);
    gemm_tc<0,0,0><<<dim3(VOCAB / BN, NTOK / BM, 1), 256, SMEM_T0>>>(
        h, wh, nullptr, out,
        NTOK, VOCAB, DMODEL, 0, 0, 0, 1.f);
}